// round 9
// baseline (speedup 1.0000x reference)
#include <cuda_runtime.h>

// Problem constants
#define NB     8
#define NH     16
#define NS     2048
#define DD     64
#define HI     256
#define NITN   4
#define CHUNK  512
#define INV_SC (1.0f / 32768.0f)     // 1/(chunk*D)

typedef unsigned long long U64;

// Final adapted weights per (b,h): [128][ W1 pair-major 16384 | W2 pair-major 16384 ]
__device__ float g_W[NB * NH * (DD * HI + HI * DD)];

// ---------------- packed f32x2 helpers --------------------------------------
__device__ __forceinline__ U64 ld64s(const float* p) {
    return *reinterpret_cast<const U64*>(p);
}
__device__ __forceinline__ void st64s(float* p, U64 v) {
    *reinterpret_cast<U64*>(p) = v;
}
__device__ __forceinline__ U64 pack2(float lo, float hi) {
    U64 r; asm("mov.b64 %0, {%1, %2};" : "=l"(r) : "f"(lo), "f"(hi)); return r;
}
__device__ __forceinline__ float2 unp2(U64 v) {
    float2 f; asm("mov.b64 {%0, %1}, %2;" : "=f"(f.x), "=f"(f.y) : "l"(v)); return f;
}
__device__ __forceinline__ U64 ffma2(U64 a, U64 b, U64 c) {
    U64 d; asm("fma.rn.f32x2 %0, %1, %2, %3;" : "=l"(d) : "l"(a), "l"(b), "l"(c));
    return d;
}

// ---------------- fast accurate tanh (MUFU.EX2 + MUFU.RCP, ~1e-7 rel) -------
__device__ __forceinline__ float fast_tanh(float u) {
    float e = __expf(2.0f * u);
    return 1.0f - __fdividef(2.0f, e + 1.0f);
}

// ---------------- gelu (tanh approximation, matches jax.nn.gelu) ------------
__device__ __forceinline__ float gelu_fwd_bwd(float x, float* dg) {
    const float c0 = 0.7978845608028654f;
    const float a0 = 0.044715f;
    float x2 = x * x;
    float u  = c0 * x * fmaf(a0, x2, 1.0f);
    float t  = fast_tanh(u);
    float du = c0 * fmaf(3.0f * a0, x2, 1.0f);
    *dg = 0.5f * (1.0f + t) + 0.5f * x * (1.0f - t * t) * du;
    return 0.5f * x * (1.0f + t);
}
__device__ __forceinline__ float gelu_f(float x) {
    const float c0 = 0.7978845608028654f;
    const float a0 = 0.044715f;
    float u = c0 * x * fmaf(a0, x * x, 1.0f);
    return 0.5f * x * (1.0f + fast_tanh(u));
}

// ---------------- training smem layout (floats) -----------------------------
// sW1p [32 d2][256 e][2]  @ 0      16384
// sW2  [256][66]          @ 16384  16896  (end 33280)
// per group g (stride 10240, base GB = 33280 + g*10240):
//   sGp [16][256] @ GB+0    (4096)
//   sH  [16][256] @ GB+4096 (4096)   (H, later dZ)
//   sX  [16][64]  @ GB+8192 (1024)
//   sE  [16][64]  @ GB+9216 (1024)
// total 53760 floats = 215040 bytes
#define OFF_W2    16384
#define OFF_GRP   33280
#define GRPSTR    10240
#define GOFF_GP   0
#define GOFF_H    4096
#define GOFF_X    8192
#define GOFF_E    9216
#define TRAIN_SMEM_BYTES (53760 * 4)

#define TTHR 512

__device__ __forceinline__ void bar_group(int gid) {
    asm volatile("bar.sync %0, 256;" :: "r"(gid + 1) : "memory");
}

__global__ __launch_bounds__(TTHR, 1)
void ttt_train_kernel(const float* __restrict__ kk, const float* __restrict__ vv,
                      const float* __restrict__ W1g, const float* __restrict__ W2g) {
    extern __shared__ float sm[];
    float* sW1p = sm;
    float* sW2  = sm + OFF_W2;   // stride 66

    const int tid  = threadIdx.x;
    const int gid  = tid >> 8;          // group 0/1
    const int gt   = tid & 255;         // thread-in-group
    const int lane = tid & 31;
    const int rg   = tid >> 5;          // global warp 0..15
    const int grg  = gt >> 5;           // group warp 0..7
    // G1 mapping (per group): rows rb*8..+8, e-quarter ch
    const int rb   = grg & 1;
    const int ch   = grg >> 1;
    // G2 mapping: rows mg..+4, col o2
    const int mg   = (gt >> 6) * 4;
    const int o2   = gt & 63;
    // G4 mapping: rows hr*8..+8, col base c0 (+128 in pass 1)
    const int hr   = gt >> 7;
    const int c0   = gt & 127;

    float* gb  = sm + OFF_GRP + gid * GRPSTR;
    float* sGp = gb + GOFF_GP;
    float* sH  = gb + GOFF_H;
    float* sX  = gb + GOFF_X;
    float* sE  = gb + GOFF_E;
    // both-group views for G3/G5
    float* sHb[2] = { sm + OFF_GRP + GOFF_H, sm + OFF_GRP + GRPSTR + GOFF_H };
    float* sEb[2] = { sm + OFF_GRP + GOFF_E, sm + OFF_GRP + GRPSTR + GOFF_E };
    float* sXb[2] = { sm + OFF_GRP + GOFF_X, sm + OFF_GRP + GRPSTR + GOFF_X };

    const int bh = blockIdx.x;
    const int h  = bh & (NH - 1);

    const float* gW1 = W1g + (size_t)h * DD * HI;
    const float* gW2 = W2g + (size_t)h * HI * DD;
    for (int i = tid; i < DD * HI; i += TTHR) {
        int d = i >> 8, e = i & 255;
        sW1p[(d >> 1) * 512 + e * 2 + (d & 1)] = gW1[i];
    }
    for (int i = tid; i < HI * DD; i += TTHR) {
        int e = i >> 6, o = i & 63;
        sW2[e * 66 + o] = gW2[i];
    }
    __syncthreads();

    const float* kb = kk + (size_t)bh * NS * DD;
    const float* vb = vv + (size_t)bh * NS * DD;

    // Persistent gradient accumulators, distributed over all 512 threads
    U64 dW1a[2][8];   // d-pair p = 2*rg+dd -> d {2p,2p+1}; e = lane+32*j
    U64 dW2a[8][2];   // e-pair pe: rows {rg*16+2pe, +1}; o = lane+32c

    for (int it = 0; it < NITN; ++it) {
        #pragma unroll
        for (int dd = 0; dd < 2; ++dd)
            #pragma unroll
            for (int j = 0; j < 8; ++j) dW1a[dd][j] = 0ull;
        #pragma unroll
        for (int pe = 0; pe < 8; ++pe) { dW2a[pe][0] = 0ull; dW2a[pe][1] = 0ull; }

        for (int st = 0; st < 16; ++st) {          // 32 rows per super-step
            const int rowbase = it * CHUNK + st * 32 + gid * 16;

            // prefetch Y for G2 (rows mg+i, col o2)
            float yv[4];
            #pragma unroll
            for (int i = 0; i < 4; ++i)
                yv[i] = vb[(size_t)(rowbase + mg + i) * DD + o2];

            // load X tile: 16x64 = 1024 floats = 256 float4 over 256 threads
            *reinterpret_cast<float4*>(&sX[gt * 4]) =
                *reinterpret_cast<const float4*>(&kb[(size_t)rowbase * DD + gt * 4]);
            bar_group(gid);

            // ---- G1: Z = X @ W1 (K-pair over d). rows rb*8..+8, two col passes
            #pragma unroll
            for (int cc = 0; cc < 2; ++cc) {
                const int col = 64 * ch + lane + 32 * cc;
                U64 acc[8];
                #pragma unroll
                for (int r = 0; r < 8; ++r) acc[r] = 0ull;
                #pragma unroll 4
                for (int dc = 0; dc < 16; ++dc) {     // 4 d per iter
                    U64 b0 = ld64s(&sW1p[(2 * dc) * 512 + col * 2]);
                    U64 b1 = ld64s(&sW1p[(2 * dc + 1) * 512 + col * 2]);
                    #pragma unroll
                    for (int r = 0; r < 8; ++r) {
                        ulonglong2 a = *reinterpret_cast<const ulonglong2*>(
                            &sX[(rb * 8 + r) * 64 + 4 * dc]);
                        acc[r] = ffma2(a.x, b0, acc[r]);
                        acc[r] = ffma2(a.y, b1, acc[r]);
                    }
                }
                #pragma unroll
                for (int r = 0; r < 8; ++r) {
                    float2 s = unp2(acc[r]);
                    float z = s.x + s.y, gp;
                    float hv = gelu_fwd_bwd(z, &gp);
                    int idx = (rb * 8 + r) * HI + col;
                    sH[idx]  = hv;
                    sGp[idx] = gp;
                }
            }
            bar_group(gid);

            // ---- G2: E = (H @ W2 - Y) * INV_SC. rows mg..+4, col o2, K=256
            {
                U64 eacc[4];
                #pragma unroll
                for (int i = 0; i < 4; ++i) eacc[i] = 0ull;
                #pragma unroll 2
                for (int ep2 = 0; ep2 < 64; ++ep2) {   // 4 e per iter
                    int e = 4 * ep2;
                    float w0 = sW2[(e + 0) * 66 + o2];
                    float w1 = sW2[(e + 1) * 66 + o2];
                    float w2 = sW2[(e + 2) * 66 + o2];
                    float w3 = sW2[(e + 3) * 66 + o2];
                    U64 b0 = pack2(w0, w1), b1 = pack2(w2, w3);
                    #pragma unroll
                    for (int i = 0; i < 4; ++i) {
                        ulonglong2 a = *reinterpret_cast<const ulonglong2*>(
                            &sH[(mg + i) * HI + e]);
                        eacc[i] = ffma2(a.x, b0, eacc[i]);
                        eacc[i] = ffma2(a.y, b1, eacc[i]);
                    }
                }
                #pragma unroll
                for (int i = 0; i < 4; ++i) {
                    float2 s = unp2(eacc[i]);
                    sE[(mg + i) * DD + o2] = (s.x + s.y - yv[i]) * INV_SC;
                }
            }
            __syncthreads();   // both groups' H and E complete

            // ---- G3: dW2 += H^T @ E  over BOTH groups (32 rows)
            //      all 512 threads: e-pairs rg*16+2pe, o = lane+32c
            #pragma unroll
            for (int g = 0; g < 2; ++g) {
                const float* bH = sHb[g];
                const float* bE = sEb[g];
                #pragma unroll 2
                for (int m = 0; m < 16; ++m) {
                    float v0 = bE[m * DD + lane];
                    float v1 = bE[m * DD + lane + 32];
                    U64 b0 = pack2(v0, v0);
                    U64 b1 = pack2(v1, v1);
                    #pragma unroll
                    for (int pe2 = 0; pe2 < 4; ++pe2) {
                        ulonglong2 a = *reinterpret_cast<const ulonglong2*>(
                            &bH[m * HI + rg * 16 + 4 * pe2]);
                        dW2a[2 * pe2][0]     = ffma2(a.x, b0, dW2a[2 * pe2][0]);
                        dW2a[2 * pe2][1]     = ffma2(a.x, b1, dW2a[2 * pe2][1]);
                        dW2a[2 * pe2 + 1][0] = ffma2(a.y, b0, dW2a[2 * pe2 + 1][0]);
                        dW2a[2 * pe2 + 1][1] = ffma2(a.y, b1, dW2a[2 * pe2 + 1][1]);
                    }
                }
            }
            __syncthreads();   // G3 done before sH overwritten with dZ

            // ---- G4: dH = E @ W2^T ; dZ = dH * gelu'
            //      rows hr*8..+8, col passes {c0, c0+128}, K-pairs over o
            #pragma unroll
            for (int cc = 0; cc < 2; ++cc) {
                const int col = c0 + 128 * cc;
                U64 g4[8];
                #pragma unroll
                for (int m = 0; m < 8; ++m) g4[m] = 0ull;
                #pragma unroll 2
                for (int op2 = 0; op2 < 16; ++op2) {   // 4 o per iter
                    U64 bA = ld64s(&sW2[col * 66 + 4 * op2]);
                    U64 bB = ld64s(&sW2[col * 66 + 4 * op2 + 2]);
                    #pragma unroll
                    for (int m = 0; m < 8; ++m) {
                        ulonglong2 a = *reinterpret_cast<const ulonglong2*>(
                            &sE[(hr * 8 + m) * DD + 4 * op2]);
                        g4[m] = ffma2(a.x, bA, g4[m]);
                        g4[m] = ffma2(a.y, bB, g4[m]);
                    }
                }
                #pragma unroll
                for (int m = 0; m < 8; ++m) {
                    float2 s = unp2(g4[m]);
                    int idx = (hr * 8 + m) * HI + col;
                    sH[idx] = (s.x + s.y) * sGp[idx];
                }
            }
            __syncthreads();   // both groups' dZ ready

            // ---- G5: dW1 += X^T @ dZ over BOTH groups (32 rows)
            //      all 512 threads: d-pairs 2rg+dd, e = lane+32j
            #pragma unroll
            for (int g = 0; g < 2; ++g) {
                const float* bX = sXb[g];
                const float* bH = sHb[g];
                #pragma unroll 2
                for (int m = 0; m < 16; ++m) {
                    ulonglong2 xx = *reinterpret_cast<const ulonglong2*>(
                        &bX[m * 64 + rg * 4]);
                    #pragma unroll
                    for (int j = 0; j < 8; ++j) {
                        float dz = bH[m * HI + lane + 32 * j];
                        U64 bz = pack2(dz, dz);
                        dW1a[0][j] = ffma2(xx.x, bz, dW1a[0][j]);
                        dW1a[1][j] = ffma2(xx.y, bz, dW1a[1][j]);
                    }
                }
            }
            __syncthreads();   // protect buffers before next super-step
        }

        // ---- SGD update (lr = 1.0), distributed over 512 threads
        #pragma unroll
        for (int dd = 0; dd < 2; ++dd)
            #pragma unroll
            for (int j = 0; j < 8; ++j) {
                int addr = (2 * rg + dd) * 512 + (lane + 32 * j) * 2;
                float2 w = unp2(ld64s(&sW1p[addr]));
                float2 g = unp2(dW1a[dd][j]);
                st64s(&sW1p[addr], pack2(w.x - g.x, w.y - g.y));
            }
        #pragma unroll
        for (int pe = 0; pe < 8; ++pe) {
            int e = rg * 16 + 2 * pe;
            #pragma unroll
            for (int c = 0; c < 2; ++c) {
                float2 g = unp2(dW2a[pe][c]);
                int o = lane + 32 * c;
                sW2[e * 66 + o]       -= g.x;
                sW2[(e + 1) * 66 + o] -= g.y;
            }
        }
        __syncthreads();
    }

    // Store final adapted weights: W1 pair-major (d), W2 pair-major (e)
    float* gw = g_W + (size_t)bh * (DD * HI + HI * DD);
    for (int i = tid; i < DD * HI; i += TTHR) gw[i] = sW1p[i];
    for (int i = tid; i < HI * DD; i += TTHR) {
        int e = i >> 6, o = i & 63;
        gw[DD * HI + (e >> 1) * 128 + o * 2 + (e & 1)] = sW2[e * 66 + o];
    }
}

// ---------------- eval: e-chunked fused MLP (unchanged, proven 460us) -------
// smem (floats): sQ [64][64] @0 | sW1c [32 d2][64 e][2] @4096 |
//                sW2c [32 e2][64 o][2] @8192 | sHc [64][64] @12288
#define EOFF_Q   0
#define EOFF_W1C 4096
#define EOFF_W2C 8192
#define EOFF_HC  12288
#define EVAL_SMEM_BYTES (16384 * 4)

__global__ __launch_bounds__(256, 2)
void ttt_eval_kernel(const float* __restrict__ qq, float* __restrict__ out) {
    extern __shared__ float sm[];
    float* sQ   = sm + EOFF_Q;
    float* sW1c = sm + EOFF_W1C;
    float* sW2c = sm + EOFF_W2C;
    float* sHc  = sm + EOFF_HC;

    const int tile = blockIdx.x;     // 0..31
    const int bh   = blockIdx.y;     // 0..127
    const int b    = bh >> 4;
    const int h    = bh & 15;
    const int tid  = threadIdx.x;
    const int lane = tid & 31;
    const int rb   = tid >> 5;       // row block (8 rows)

    const float* gw  = g_W + (size_t)bh * (DD * HI + HI * DD);
    const float* gw2 = gw + DD * HI;
    const float* qb  = qq + ((size_t)bh * NS + tile * 64) * DD;

    // load Q tile (plain, float4)
    #pragma unroll
    for (int r = 0; r < 4; ++r) {
        int i4 = tid + 256 * r;
        *reinterpret_cast<float4*>(&sQ[i4 * 4]) =
            *reinterpret_cast<const float4*>(&qb[i4 * 4]);
    }

    U64 oacc[8][2];   // rows rb*8+i, cols {lane, lane+32}; K-pair over e
    #pragma unroll
    for (int i = 0; i < 8; ++i) { oacc[i][0] = 0ull; oacc[i][1] = 0ull; }

    for (int c = 0; c < 4; ++c) {
        __syncthreads();   // previous chunk consumers done (covers sQ fill too)
        // load W1 chunk: rows d2, 128 consecutive floats each
        #pragma unroll
        for (int r = 0; r < 4; ++r) {
            int i4 = tid + 256 * r;
            int d2 = i4 >> 5, off = (i4 & 31) * 4;
            *reinterpret_cast<float4*>(&sW1c[d2 * 128 + off]) =
                *reinterpret_cast<const float4*>(&gw[d2 * 512 + c * 128 + off]);
        }
        // load W2 chunk: contiguous 4096 floats
        #pragma unroll
        for (int r = 0; r < 4; ++r) {
            int i4 = tid + 256 * r;
            *reinterpret_cast<float4*>(&sW2c[i4 * 4]) =
                *reinterpret_cast<const float4*>(&gw2[c * 4096 + i4 * 4]);
        }
        __syncthreads();

        // Z chunk: rows rb*8..+8, e-cols {lane, lane+32}, K-pair over d
        {
            U64 zacc[8][2];
            #pragma unroll
            for (int i = 0; i < 8; ++i) { zacc[i][0] = 0ull; zacc[i][1] = 0ull; }
            #pragma unroll 4
            for (int dc = 0; dc < 16; ++dc) {    // 4 d per iter
                ulonglong2 aa[8];
                #pragma unroll
                for (int r = 0; r < 8; ++r)
                    aa[r] = *reinterpret_cast<const ulonglong2*>(
                        &sQ[(rb * 8 + r) * 64 + 4 * dc]);
                U64 b00 = ld64s(&sW1c[(2 * dc) * 128 + lane * 2]);
                U64 b01 = ld64s(&sW1c[(2 * dc + 1) * 128 + lane * 2]);
                U64 b10 = ld64s(&sW1c[(2 * dc) * 128 + (lane + 32) * 2]);
                U64 b11 = ld64s(&sW1c[(2 * dc + 1) * 128 + (lane + 32) * 2]);
                #pragma unroll
                for (int r = 0; r < 8; ++r) {
                    zacc[r][0] = ffma2(aa[r].x, b00, zacc[r][0]);
                    zacc[r][0] = ffma2(aa[r].y, b01, zacc[r][0]);
                    zacc[r][1] = ffma2(aa[r].x, b10, zacc[r][1]);
                    zacc[r][1] = ffma2(aa[r].y, b11, zacc[r][1]);
                }
            }
            #pragma unroll
            for (int r = 0; r < 8; ++r)
                #pragma unroll
                for (int g = 0; g < 2; ++g) {
                    float2 s = unp2(zacc[r][g]);
                    sHc[(rb * 8 + r) * 64 + lane + 32 * g] = gelu_f(s.x + s.y);
                }
        }
        __syncthreads();

        // O partial: rows rb*8..+8, cols {lane, lane+32}, K-pair over chunk e
        #pragma unroll 2
        for (int ec = 0; ec < 16; ++ec) {       // 4 e per iter (2 e-pairs)
            U64 b00 = ld64s(&sW2c[(2 * ec) * 128 + lane * 2]);
            U64 b01 = ld64s(&sW2c[(2 * ec + 1) * 128 + lane * 2]);
            U64 b10 = ld64s(&sW2c[(2 * ec) * 128 + (lane + 32) * 2]);
            U64 b11 = ld64s(&sW2c[(2 * ec + 1) * 128 + (lane + 32) * 2]);
            #pragma unroll
            for (int i = 0; i < 8; ++i) {
                ulonglong2 a = *reinterpret_cast<const ulonglong2*>(
                    &sHc[(rb * 8 + i) * 64 + 4 * ec]);
                oacc[i][0] = ffma2(a.x, b00, oacc[i][0]);
                oacc[i][0] = ffma2(a.y, b01, oacc[i][0]);
                oacc[i][1] = ffma2(a.x, b10, oacc[i][1]);
                oacc[i][1] = ffma2(a.y, b11, oacc[i][1]);
            }
        }
    }

    // write out[b, n, h*64 + o]
    #pragma unroll
    for (int i = 0; i < 8; ++i) {
        float2 s0 = unp2(oacc[i][0]);
        float2 s1 = unp2(oacc[i][1]);
        int n = tile * 64 + rb * 8 + i;
        size_t base = ((size_t)b * NS + n) * (NH * DD) + h * DD;
        out[base + lane]      = s0.x + s0.y;
        out[base + lane + 32] = s1.x + s1.y;
    }
}

extern "C" void kernel_launch(void* const* d_in, const int* in_sizes, int n_in,
                              void* d_out, int out_size) {
    const float* q  = (const float*)d_in[0];
    const float* k  = (const float*)d_in[1];
    const float* v  = (const float*)d_in[2];
    const float* W1 = (const float*)d_in[3];
    const float* W2 = (const float*)d_in[4];
    float* out = (float*)d_out;

    cudaFuncSetAttribute(ttt_train_kernel,
                         cudaFuncAttributeMaxDynamicSharedMemorySize, TRAIN_SMEM_BYTES);
    cudaFuncSetAttribute(ttt_eval_kernel,
                         cudaFuncAttributeMaxDynamicSharedMemorySize, EVAL_SMEM_BYTES);

    ttt_train_kernel<<<NB * NH, TTHR, TRAIN_SMEM_BYTES>>>(k, v, W1, W2);
    ttt_eval_kernel<<<dim3(NS / 64, NB * NH), 256, EVAL_SMEM_BYTES>>>(q, out);
}

// round 13
// speedup vs baseline: 1.1080x; 1.1080x over previous
#include <cuda_runtime.h>

// Problem constants
#define NB     8
#define NH     16
#define NS     2048
#define DD     64
#define HI     256
#define NITN   4
#define CHUNK  512
#define MT     32
#define NTILE  (CHUNK / MT)          // 16
#define INV_SC (1.0f / 32768.0f)     // 1/(chunk*D)

typedef unsigned long long U64;

// Final adapted weights per (b,h).
// W1 stored in interleaved-quad layout:
//   W1[d][e] at (d>>1)*512 + (e>>6)*128 + (e&31)*4 + ((e>>5)&1)*2 + (d&1)
// W2 stored in interleaved-quad layout:
//   W2[e][o] at (e>>1)*128 + (o&31)*4 + ((o>>5)&1)*2 + (e&1)   (+ DD*HI base)
__device__ float g_W[NB * NH * (DD * HI + HI * DD)];

// ---------------- packed f32x2 helpers --------------------------------------
__device__ __forceinline__ U64 ld64s(const float* p) {
    return *reinterpret_cast<const U64*>(p);
}
__device__ __forceinline__ void st64s(float* p, U64 v) {
    *reinterpret_cast<U64*>(p) = v;
}
__device__ __forceinline__ U64 pack2(float lo, float hi) {
    U64 r; asm("mov.b64 %0, {%1, %2};" : "=l"(r) : "f"(lo), "f"(hi)); return r;
}
__device__ __forceinline__ float2 unp2(U64 v) {
    float2 f; asm("mov.b64 {%0, %1}, %2;" : "=f"(f.x), "=f"(f.y) : "l"(v)); return f;
}
__device__ __forceinline__ U64 ffma2(U64 a, U64 b, U64 c) {
    U64 d; asm("fma.rn.f32x2 %0, %1, %2, %3;" : "=l"(d) : "l"(a), "l"(b), "l"(c));
    return d;
}

// ---------------- fast accurate tanh (MUFU.EX2 + MUFU.RCP, ~1e-7 rel) -------
__device__ __forceinline__ float fast_tanh(float u) {
    float e = __expf(2.0f * u);
    return 1.0f - __fdividef(2.0f, e + 1.0f);
}

// ---------------- gelu (tanh approximation, matches jax.nn.gelu) ------------
__device__ __forceinline__ float gelu_fwd_bwd(float x, float* dg) {
    const float c0 = 0.7978845608028654f;
    const float a0 = 0.044715f;
    float x2 = x * x;
    float u  = c0 * x * fmaf(a0, x2, 1.0f);
    float t  = fast_tanh(u);
    float du = c0 * fmaf(3.0f * a0, x2, 1.0f);
    *dg = 0.5f * (1.0f + t) + 0.5f * x * (1.0f - t * t) * du;
    return 0.5f * x * (1.0f + t);
}
__device__ __forceinline__ float gelu_f(float x) {
    const float c0 = 0.7978845608028654f;
    const float a0 = 0.044715f;
    float u = c0 * x * fmaf(a0, x * x, 1.0f);
    return 0.5f * x * (1.0f + fast_tanh(u));
}

// ---------------- training smem layout (floats) -----------------------------
// sW1i [interleaved quad]   @ 0      16384
// sW2  [256][66]            @ 16384  16896
// sGp  [32][256]            @ 33280   8192
// sH   [32][256]            @ 41472   8192   (H, later overwritten with dZ)
// sX   [32][64]             @ 49664   2048
// sE   [32][64]             @ 51712   2048
#define OFF_W1P 0
#define OFF_W2  16384
#define OFF_GP  33280
#define OFF_H   41472
#define OFF_X   49664
#define OFF_E   51712
#define TRAIN_SMEM_BYTES (53760 * 4)

__global__ __launch_bounds__(256, 1)
void ttt_train_kernel(const float* __restrict__ kk, const float* __restrict__ vv,
                      const float* __restrict__ W1g, const float* __restrict__ W2g) {
    extern __shared__ float sm[];
    float* sW1i = sm + OFF_W1P;
    float* sW2  = sm + OFF_W2;   // stride 66
    float* sGp  = sm + OFF_GP;
    float* sH   = sm + OFF_H;
    float* sX   = sm + OFF_X;
    float* sE   = sm + OFF_E;

    const int bh   = blockIdx.x;
    const int h    = bh & (NH - 1);
    const int tid  = threadIdx.x;
    const int lane = tid & 31;
    const int rg   = tid >> 5;          // warp 0..7
    // G1 mapping
    const int rb   = rg & 3;            // row block (8 rows)
    const int ch   = rg >> 2;           // e quarter selector (two quarters/warp via cols)
    // G2 mapping
    const int o2   = tid & 63;          // output col
    const int mg   = (tid >> 6) * 8;    // row base (8 rows)
    // G4 mapping
    const int hr   = tid >> 7;          // row half (16 rows)
    const int c0   = tid & 127;         // dH column base

    const float* gW1 = W1g + (size_t)h * DD * HI;
    const float* gW2 = W2g + (size_t)h * HI * DD;
    for (int i = tid; i < DD * HI; i += 256) {
        int d = i >> 8, e = i & 255;
        sW1i[(d >> 1) * 512 + (e >> 6) * 128 + (e & 31) * 4 + ((e >> 5) & 1) * 2 + (d & 1)] = gW1[i];
    }
    for (int i = tid; i < HI * DD; i += 256) {
        int e = i >> 6, o = i & 63;
        sW2[e * 66 + o] = gW2[i];
    }
    __syncthreads();

    const float* kb = kk + (size_t)bh * NS * DD;
    const float* vb = vv + (size_t)bh * NS * DD;

    // Persistent gradient accumulators
    U64 dW1a[4][8];   // d-pair p = rg*4+pp ; e = lane+32*j -> {dW1[2p][e], dW1[2p+1][e]}
    U64 dW2a[16][2];  // e-pair pe: rows {rg*32+2pe, +1}; o = lane+32c

    for (int it = 0; it < NITN; ++it) {
        #pragma unroll
        for (int pp = 0; pp < 4; ++pp)
            #pragma unroll
            for (int j = 0; j < 8; ++j) dW1a[pp][j] = 0ull;
        #pragma unroll
        for (int pe = 0; pe < 16; ++pe) { dW2a[pe][0] = 0ull; dW2a[pe][1] = 0ull; }

        for (int mt = 0; mt < NTILE; ++mt) {
            const int rowbase = it * CHUNK + mt * MT;

            // prefetch Y for the G2 epilogue (rows mg+i, col o2)
            float yv[8];
            #pragma unroll
            for (int i = 0; i < 8; ++i)
                yv[i] = vb[(size_t)(rowbase + mg + i) * DD + o2];

            // load X tile (plain layout, float4)
            #pragma unroll
            for (int r = 0; r < 2; ++r) {
                int i4 = tid + 256 * r;
                *reinterpret_cast<float4*>(&sX[i4 * 4]) =
                    *reinterpret_cast<const float4*>(&kb[(size_t)rowbase * DD + i4 * 4]);
            }
            __syncthreads();

            // ---- G1: Z = X @ W1 (K-pair over d). rows rb*8..+8, cols {e0, e0+32}
            //      quad B-loads: one LDS.128 per d2 covers both cols
            {
                const int e0 = 64 * ch * 2 + lane;      // quarter q = 2*ch? no: see below
                // NOTE: ch in {0,1}; warps rb cover rows, ch selects e-quarter pair.
                // We process quarters q = ch*2 and ch*2+1 via two col-pass? No —
                // round-6 shape: each warp owns ONE 64-col quarter pair {e0, e0+32}
                // within quarter q = ch*2 .. use two passes over quarters.
                U64 dummy = 0; (void)dummy; (void)e0;
            }
            #pragma unroll
            for (int pass = 0; pass < 2; ++pass) {
                const int q  = ch * 2 + pass;           // e-quarter 0..3
                const int e0 = q * 64 + lane;           // col 0; col 1 = e0+32
                U64 acc[8][2];
                #pragma unroll
                for (int r = 0; r < 8; ++r) { acc[r][0] = 0ull; acc[r][1] = 0ull; }
                #pragma unroll 4
                for (int dc = 0; dc < 16; ++dc) {       // 4 d per iter
                    ulonglong2 qA = *reinterpret_cast<const ulonglong2*>(
                        &sW1i[(2 * dc) * 512 + q * 128 + lane * 4]);
                    ulonglong2 qB = *reinterpret_cast<const ulonglong2*>(
                        &sW1i[(2 * dc + 1) * 512 + q * 128 + lane * 4]);
                    // qA.x = d{4dc,4dc+1}@e0   qA.y = @e0+32
                    // qB.x = d{4dc+2,4dc+3}@e0 qB.y = @e0+32
                    #pragma unroll
                    for (int r = 0; r < 8; ++r) {
                        ulonglong2 a = *reinterpret_cast<const ulonglong2*>(
                            &sX[(rb * 8 + r) * 64 + 4 * dc]);
                        acc[r][0] = ffma2(a.x, qA.x, acc[r][0]);
                        acc[r][0] = ffma2(a.y, qB.x, acc[r][0]);
                        acc[r][1] = ffma2(a.x, qA.y, acc[r][1]);
                        acc[r][1] = ffma2(a.y, qB.y, acc[r][1]);
                    }
                }
                #pragma unroll
                for (int r = 0; r < 8; ++r)
                    #pragma unroll
                    for (int c = 0; c < 2; ++c) {
                        float2 s = unp2(acc[r][c]);
                        float z = s.x + s.y, gp;
                        float hv = gelu_fwd_bwd(z, &gp);
                        int idx = (rb * 8 + r) * HI + e0 + 32 * c;
                        sH[idx]  = hv;
                        sGp[idx] = gp;
                    }
            }
            __syncthreads();

            // ---- G2: E = (H @ W2 - Y) * INV_SC. rows mg+i, col o2, K-pairs over e
            {
                U64 eacc[8];
                #pragma unroll
                for (int i = 0; i < 8; ++i) eacc[i] = 0ull;
                #pragma unroll 2
                for (int ep2 = 0; ep2 < 64; ++ep2) {   // 4 e per iter
                    float w0 = sW2[(4 * ep2 + 0) * 66 + o2];
                    float w1 = sW2[(4 * ep2 + 1) * 66 + o2];
                    float w2 = sW2[(4 * ep2 + 2) * 66 + o2];
                    float w3 = sW2[(4 * ep2 + 3) * 66 + o2];
                    U64 b0 = pack2(w0, w1), b1 = pack2(w2, w3);
                    #pragma unroll
                    for (int i = 0; i < 8; ++i) {
                        ulonglong2 a = *reinterpret_cast<const ulonglong2*>(
                            &sH[(mg + i) * HI + 4 * ep2]);
                        eacc[i] = ffma2(a.x, b0, eacc[i]);
                        eacc[i] = ffma2(a.y, b1, eacc[i]);
                    }
                }
                #pragma unroll
                for (int i = 0; i < 8; ++i) {
                    float2 s = unp2(eacc[i]);
                    sE[(mg + i) * DD + o2] = (s.x + s.y - yv[i]) * INV_SC;
                }
            }
            __syncthreads();

            // ---- G3: dW2 += H^T @ E  (e-pairs rg*32+2pe, o = lane+32c)
            #pragma unroll 2
            for (int m = 0; m < MT; ++m) {
                float v0 = sE[m * DD + lane];
                float v1 = sE[m * DD + lane + 32];
                U64 b0 = pack2(v0, v0);
                U64 b1 = pack2(v1, v1);
                #pragma unroll
                for (int pe2 = 0; pe2 < 8; ++pe2) {    // 4 e per iter (2 pairs)
                    ulonglong2 a = *reinterpret_cast<const ulonglong2*>(
                        &sH[m * HI + rg * 32 + 4 * pe2]);
                    dW2a[2 * pe2][0]     = ffma2(a.x, b0, dW2a[2 * pe2][0]);
                    dW2a[2 * pe2][1]     = ffma2(a.x, b1, dW2a[2 * pe2][1]);
                    dW2a[2 * pe2 + 1][0] = ffma2(a.y, b0, dW2a[2 * pe2 + 1][0]);
                    dW2a[2 * pe2 + 1][1] = ffma2(a.y, b1, dW2a[2 * pe2 + 1][1]);
                }
            }

            // ---- G4: dH = E @ W2^T ; dZ = dH * gelu'
            //      rows hr*16..+16, cols {c0, c0+128}, K-pairs over o
            {
                U64 g4[16][2];
                #pragma unroll
                for (int m = 0; m < 16; ++m) { g4[m][0] = 0ull; g4[m][1] = 0ull; }
                #pragma unroll 2
                for (int op2 = 0; op2 < 16; ++op2) {   // 4 o per iter
                    U64 b0a = ld64s(&sW2[c0 * 66 + 4 * op2]);
                    U64 b0b = ld64s(&sW2[c0 * 66 + 4 * op2 + 2]);
                    U64 b1a = ld64s(&sW2[(c0 + 128) * 66 + 4 * op2]);
                    U64 b1b = ld64s(&sW2[(c0 + 128) * 66 + 4 * op2 + 2]);
                    #pragma unroll
                    for (int m = 0; m < 16; ++m) {
                        ulonglong2 a = *reinterpret_cast<const ulonglong2*>(
                            &sE[(hr * 16 + m) * DD + 4 * op2]);
                        g4[m][0] = ffma2(a.x, b0a, g4[m][0]);
                        g4[m][0] = ffma2(a.y, b0b, g4[m][0]);
                        g4[m][1] = ffma2(a.x, b1a, g4[m][1]);
                        g4[m][1] = ffma2(a.y, b1b, g4[m][1]);
                    }
                }
                __syncthreads();   // all G3 reads of sH done before overwrite
                #pragma unroll
                for (int m = 0; m < 16; ++m) {
                    float2 s0 = unp2(g4[m][0]);
                    float2 s1 = unp2(g4[m][1]);
                    int idx = (hr * 16 + m) * HI + c0;
                    sH[idx]       = (s0.x + s0.y) * sGp[idx];
                    sH[idx + 128] = (s1.x + s1.y) * sGp[idx + 128];
                }
            }
            __syncthreads();

            // ---- G5: dW1 += X^T @ dZ  (d-pairs rg*4+pp, e = lane+32j)
            #pragma unroll 2
            for (int m = 0; m < MT; ++m) {
                ulonglong2 x01 = *reinterpret_cast<const ulonglong2*>(&sX[m * 64 + rg * 8]);
                ulonglong2 x23 = *reinterpret_cast<const ulonglong2*>(&sX[m * 64 + rg * 8 + 4]);
                #pragma unroll
                for (int j = 0; j < 8; ++j) {
                    float dz = sH[m * HI + lane + 32 * j];
                    U64 bz = pack2(dz, dz);
                    dW1a[0][j] = ffma2(x01.x, bz, dW1a[0][j]);
                    dW1a[1][j] = ffma2(x01.y, bz, dW1a[1][j]);
                    dW1a[2][j] = ffma2(x23.x, bz, dW1a[2][j]);
                    dW1a[3][j] = ffma2(x23.y, bz, dW1a[3][j]);
                }
            }
            __syncthreads();   // protect sX/sH/sE before next tile
        }

        // ---- SGD update (lr = 1.0); W1 addressing in interleaved-quad layout
        #pragma unroll
        for (int pp = 0; pp < 4; ++pp)
            #pragma unroll
            for (int j = 0; j < 8; ++j) {
                int addr = (rg * 4 + pp) * 512 + (j >> 1) * 128 + lane * 4 + (j & 1) * 2;
                float2 w = unp2(ld64s(&sW1i[addr]));
                float2 g = unp2(dW1a[pp][j]);
                st64s(&sW1i[addr], pack2(w.x - g.x, w.y - g.y));
            }
        #pragma unroll
        for (int pe = 0; pe < 16; ++pe) {
            int e = rg * 32 + 2 * pe;
            #pragma unroll
            for (int c = 0; c < 2; ++c) {
                float2 g = unp2(dW2a[pe][c]);
                int o = lane + 32 * c;
                sW2[e * 66 + o]       -= g.x;
                sW2[(e + 1) * 66 + o] -= g.y;
            }
        }
        __syncthreads();
    }

    // Store final adapted weights: W1 raw (already interleaved), W2 -> quad layout
    float* gw = g_W + (size_t)bh * (DD * HI + HI * DD);
    for (int i = tid; i < DD * HI; i += 256) gw[i] = sW1i[i];
    for (int i = tid; i < HI * DD; i += 256) {
        int e = i >> 6, o = i & 63;
        gw[DD * HI + (e >> 1) * 128 + (o & 31) * 4 + ((o >> 5) & 1) * 2 + (e & 1)]
            = sW2[e * 66 + o];
    }
}

// ---------------- eval: e-chunked fused MLP, quad B-loads -------------------
// smem (floats): sQ [64][64] @0 | sW1c quad-chunk @4096 |
//                sW2c quad-chunk @8192 | sHc [64][64] @12288
#define EOFF_Q   0
#define EOFF_W1C 4096
#define EOFF_W2C 8192
#define EOFF_HC  12288
#define EVAL_SMEM_BYTES (16384 * 4)

__global__ __launch_bounds__(256, 2)
void ttt_eval_kernel(const float* __restrict__ qq, float* __restrict__ out) {
    extern __shared__ float sm[];
    float* sQ   = sm + EOFF_Q;
    float* sW1c = sm + EOFF_W1C;
    float* sW2c = sm + EOFF_W2C;
    float* sHc  = sm + EOFF_HC;

    const int tile = blockIdx.x;     // 0..31
    const int bh   = blockIdx.y;     // 0..127
    const int b    = bh >> 4;
    const int h    = bh & 15;
    const int tid  = threadIdx.x;
    const int lane = tid & 31;
    const int rb   = tid >> 5;       // row block (8 rows)

    const float* gw  = g_W + (size_t)bh * (DD * HI + HI * DD);
    const float* gw2 = gw + DD * HI;
    const float* qb  = qq + ((size_t)bh * NS + tile * 64) * DD;

    // load Q tile (plain, float4)
    #pragma unroll
    for (int r = 0; r < 4; ++r) {
        int i4 = tid + 256 * r;
        *reinterpret_cast<float4*>(&sQ[i4 * 4]) =
            *reinterpret_cast<const float4*>(&qb[i4 * 4]);
    }

    U64 oacc[8][2];   // rows rb*8+i, cols {lane, lane+32}; K-pair over e
    #pragma unroll
    for (int i = 0; i < 8; ++i) { oacc[i][0] = 0ull; oacc[i][1] = 0ull; }

    for (int c = 0; c < 4; ++c) {
        __syncthreads();   // previous chunk consumers done (covers sQ fill too)
        // load W1 chunk (quarter q=c slice of interleaved layout: contiguous per d2)
        #pragma unroll
        for (int r = 0; r < 4; ++r) {
            int i4 = tid + 256 * r;
            int d2 = i4 >> 5, off = (i4 & 31) * 4;
            *reinterpret_cast<float4*>(&sW1c[d2 * 128 + off]) =
                *reinterpret_cast<const float4*>(&gw[d2 * 512 + c * 128 + off]);
        }
        // load W2 chunk: contiguous 4096 floats of quad layout
        #pragma unroll
        for (int r = 0; r < 4; ++r) {
            int i4 = tid + 256 * r;
            *reinterpret_cast<float4*>(&sW2c[i4 * 4]) =
                *reinterpret_cast<const float4*>(&gw2[c * 4096 + i4 * 4]);
        }
        __syncthreads();

        // Z chunk: rows rb*8..+8, e-cols {lane, lane+32}, K-pair over d, quad B
        {
            U64 zacc[8][2];
            #pragma unroll
            for (int i = 0; i < 8; ++i) { zacc[i][0] = 0ull; zacc[i][1] = 0ull; }
            #pragma unroll 4
            for (int dc = 0; dc < 16; ++dc) {    // 4 d per iter
                ulonglong2 qA = *reinterpret_cast<const ulonglong2*>(
                    &sW1c[(2 * dc) * 128 + lane * 4]);
                ulonglong2 qB = *reinterpret_cast<const ulonglong2*>(
                    &sW1c[(2 * dc + 1) * 128 + lane * 4]);
                // qA.x = d{4dc,4dc+1}@lane   qA.y = @lane+32
                // qB.x = d{4dc+2,4dc+3}@lane qB.y = @lane+32
                #pragma unroll
                for (int r = 0; r < 8; ++r) {
                    ulonglong2 a = *reinterpret_cast<const ulonglong2*>(
                        &sQ[(rb * 8 + r) * 64 + 4 * dc]);
                    zacc[r][0] = ffma2(a.x, qA.x, zacc[r][0]);
                    zacc[r][0] = ffma2(a.y, qB.x, zacc[r][0]);
                    zacc[r][1] = ffma2(a.x, qA.y, zacc[r][1]);
                    zacc[r][1] = ffma2(a.y, qB.y, zacc[r][1]);
                }
            }
            #pragma unroll
            for (int r = 0; r < 8; ++r)
                #pragma unroll
                for (int g = 0; g < 2; ++g) {
                    float2 s = unp2(zacc[r][g]);
                    sHc[(rb * 8 + r) * 64 + lane + 32 * g] = gelu_f(s.x + s.y);
                }
        }
        __syncthreads();

        // O partial: rows rb*8..+8, cols {lane, lane+32}, K-pair over e, quad B
        #pragma unroll 2
        for (int ec = 0; ec < 16; ++ec) {       // 4 e per iter
            ulonglong2 qA = *reinterpret_cast<const ulonglong2*>(
                &sW2c[(2 * ec) * 128 + lane * 4]);
            ulonglong2 qB = *reinterpret_cast<const ulonglong2*>(
                &sW2c[(2 * ec + 1) * 128 + lane * 4]);
            #pragma unroll
            for (int i = 0; i < 8; ++i) {
                ulonglong2 a = *reinterpret_cast<const ulonglong2*>(
                    &sHc[(rb * 8 + i) * 64 + 4 * ec]);
                oacc[i][0] = ffma2(a.x, qA.x, oacc[i][0]);
                oacc[i][0] = ffma2(a.y, qB.x, oacc[i][0]);
                oacc[i][1] = ffma2(a.x, qA.y, oacc[i][1]);
                oacc[i][1] = ffma2(a.y, qB.y, oacc[i][1]);
            }
        }
    }

    // write out[b, n, h*64 + o]
    #pragma unroll
    for (int i = 0; i < 8; ++i) {
        float2 s0 = unp2(oacc[i][0]);
        float2 s1 = unp2(oacc[i][1]);
        int n = tile * 64 + rb * 8 + i;
        size_t base = ((size_t)b * NS + n) * (NH * DD) + h * DD;
        out[base + lane]      = s0.x + s0.y;
        out[base + lane + 32] = s1.x + s1.y;
    }
}

extern "C" void kernel_launch(void* const* d_in, const int* in_sizes, int n_in,
                              void* d_out, int out_size) {
    const float* q  = (const float*)d_in[0];
    const float* k  = (const float*)d_in[1];
    const float* v  = (const float*)d_in[2];
    const float* W1 = (const float*)d_in[3];
    const float* W2 = (const float*)d_in[4];
    float* out = (float*)d_out;

    cudaFuncSetAttribute(ttt_train_kernel,
                         cudaFuncAttributeMaxDynamicSharedMemorySize, TRAIN_SMEM_BYTES);
    cudaFuncSetAttribute(ttt_eval_kernel,
                         cudaFuncAttributeMaxDynamicSharedMemorySize, EVAL_SMEM_BYTES);

    ttt_train_kernel<<<NB * NH, 256, TRAIN_SMEM_BYTES>>>(k, v, W1, W2);
    ttt_eval_kernel<<<dim3(NS / 64, NB * NH), 256, EVAL_SMEM_BYTES>>>(q, out);
}

// round 14
// speedup vs baseline: 1.1550x; 1.0424x over previous
#include <cuda_runtime.h>

// Problem constants
#define NB     8
#define NH     16
#define NS     2048
#define DD     64
#define HI     256
#define NITN   4
#define CHUNK  512
#define MT     32
#define NTILE  (CHUNK / MT)          // 16
#define INV_SC (1.0f / 32768.0f)     // 1/(chunk*D)

typedef unsigned long long U64;

// Final adapted weights per (b,h): [128][ W1 pair-major 16384 | W2 pair-major 16384 ]
// W1[d][e] at (d>>1)*512 + e*2 + (d&1)
// W2[e][o] at (e>>1)*128 + o*2 + (e&1)   (+ DD*HI base)
__device__ float g_W[NB * NH * (DD * HI + HI * DD)];

// ---------------- packed f32x2 helpers --------------------------------------
__device__ __forceinline__ U64 ld64s(const float* p) {
    return *reinterpret_cast<const U64*>(p);
}
__device__ __forceinline__ void st64s(float* p, U64 v) {
    *reinterpret_cast<U64*>(p) = v;
}
__device__ __forceinline__ U64 pack2(float lo, float hi) {
    U64 r; asm("mov.b64 %0, {%1, %2};" : "=l"(r) : "f"(lo), "f"(hi)); return r;
}
__device__ __forceinline__ float2 unp2(U64 v) {
    float2 f; asm("mov.b64 {%0, %1}, %2;" : "=f"(f.x), "=f"(f.y) : "l"(v)); return f;
}
__device__ __forceinline__ U64 ffma2(U64 a, U64 b, U64 c) {
    U64 d; asm("fma.rn.f32x2 %0, %1, %2, %3;" : "=l"(d) : "l"(a), "l"(b), "l"(c));
    return d;
}

// ---------------- fast accurate tanh (MUFU.EX2 + MUFU.RCP, ~1e-7 rel) -------
__device__ __forceinline__ float fast_tanh(float u) {
    float e = __expf(2.0f * u);
    return 1.0f - __fdividef(2.0f, e + 1.0f);
}

// ---------------- gelu (tanh approximation, matches jax.nn.gelu) ------------
__device__ __forceinline__ float gelu_fwd_bwd(float x, float* dg) {
    const float c0 = 0.7978845608028654f;
    const float a0 = 0.044715f;
    float x2 = x * x;
    float u  = c0 * x * fmaf(a0, x2, 1.0f);
    float t  = fast_tanh(u);
    float du = c0 * fmaf(3.0f * a0, x2, 1.0f);
    *dg = 0.5f * (1.0f + t) + 0.5f * x * (1.0f - t * t) * du;
    return 0.5f * x * (1.0f + t);
}
__device__ __forceinline__ float gelu_f(float x) {
    const float c0 = 0.7978845608028654f;
    const float a0 = 0.044715f;
    float u = c0 * x * fmaf(a0, x * x, 1.0f);
    return 0.5f * x * (1.0f + fast_tanh(u));
}

// ---------------- training smem layout (floats) -----------------------------
// sW1p [32 d2][256 e][2]  @ 0      16384
// sW2  [256][66]          @ 16384  16896
// sGp  [32][256]          @ 33280   8192   (gelu', overwritten in-place with dZ)
// sH   [32][256]          @ 41472   8192
// sX   [32][64]           @ 49664   2048
// sE   [32][64]           @ 51712   2048
#define OFF_W1P 0
#define OFF_W2  16384
#define OFF_GP  33280
#define OFF_H   41472
#define OFF_X   49664
#define OFF_E   51712
#define TRAIN_SMEM_BYTES (53760 * 4)

__global__ __launch_bounds__(256, 1)
void ttt_train_kernel(const float* __restrict__ kk, const float* __restrict__ vv,
                      const float* __restrict__ W1g, const float* __restrict__ W2g) {
    extern __shared__ float sm[];
    float* sW1p = sm + OFF_W1P;
    float* sW2  = sm + OFF_W2;   // stride 66
    float* sGp  = sm + OFF_GP;
    float* sH   = sm + OFF_H;
    float* sX   = sm + OFF_X;
    float* sE   = sm + OFF_E;

    const int bh   = blockIdx.x;
    const int h    = bh & (NH - 1);
    const int tid  = threadIdx.x;
    const int lane = tid & 31;
    const int rg   = tid >> 5;          // warp 0..7
    // G1 mapping: 2 row-blocks of 16 x 4 e-quarters
    const int rb1  = rg & 1;            // row block (16 rows)
    const int q1   = rg >> 1;           // e quarter (64 cols)
    // G2 mapping
    const int o2   = tid & 63;          // output col
    const int mg   = (tid >> 6) * 8;    // row base (8 rows)
    // G4 mapping
    const int hr   = tid >> 7;          // row half (16 rows)
    const int c0   = tid & 127;         // dH column base

    const float* gW1 = W1g + (size_t)h * DD * HI;
    const float* gW2 = W2g + (size_t)h * HI * DD;
    for (int i = tid; i < DD * HI; i += 256) {
        int d = i >> 8, e = i & 255;
        sW1p[(d >> 1) * 512 + e * 2 + (d & 1)] = gW1[i];
    }
    for (int i = tid; i < HI * DD; i += 256) {
        int e = i >> 6, o = i & 63;
        sW2[e * 66 + o] = gW2[i];
    }
    __syncthreads();

    const float* kb = kk + (size_t)bh * NS * DD;
    const float* vb = vv + (size_t)bh * NS * DD;

    // Persistent gradient accumulators
    U64 dW1a[4][8];   // d-pair p = rg*4+pp ; e = lane+32*j -> {dW1[2p][e], dW1[2p+1][e]}
    U64 dW2a[16][2];  // e-pair pe: rows {rg*32+2pe, +1}; o = lane+32c

    for (int it = 0; it < NITN; ++it) {
        #pragma unroll
        for (int pp = 0; pp < 4; ++pp)
            #pragma unroll
            for (int j = 0; j < 8; ++j) dW1a[pp][j] = 0ull;
        #pragma unroll
        for (int pe = 0; pe < 16; ++pe) { dW2a[pe][0] = 0ull; dW2a[pe][1] = 0ull; }

        for (int mt = 0; mt < NTILE; ++mt) {
            const int rowbase = it * CHUNK + mt * MT;

            // prefetch Y for the G2 epilogue (rows mg+i, col o2)
            float yv[8];
            #pragma unroll
            for (int i = 0; i < 8; ++i)
                yv[i] = vb[(size_t)(rowbase + mg + i) * DD + o2];

            // load X tile (plain layout, float4)
            #pragma unroll
            for (int r = 0; r < 2; ++r) {
                int i4 = tid + 256 * r;
                *reinterpret_cast<float4*>(&sX[i4 * 4]) =
                    *reinterpret_cast<const float4*>(&kb[(size_t)rowbase * DD + i4 * 4]);
            }
            __syncthreads();

            // ---- G1: Z = X @ W1 (K-pair over d), single pass.
            //      rows rb1*16..+16, cols {e0, e0+32}
            {
                const int e0 = q1 * 64 + lane;
                U64 acc[16][2];
                #pragma unroll
                for (int r = 0; r < 16; ++r) { acc[r][0] = 0ull; acc[r][1] = 0ull; }
                #pragma unroll 4
                for (int dc = 0; dc < 16; ++dc) {       // 4 d per iter
                    U64 b00 = ld64s(&sW1p[(2 * dc) * 512 + e0 * 2]);
                    U64 b01 = ld64s(&sW1p[(2 * dc + 1) * 512 + e0 * 2]);
                    U64 b10 = ld64s(&sW1p[(2 * dc) * 512 + (e0 + 32) * 2]);
                    U64 b11 = ld64s(&sW1p[(2 * dc + 1) * 512 + (e0 + 32) * 2]);
                    #pragma unroll
                    for (int r = 0; r < 16; ++r) {
                        ulonglong2 a = *reinterpret_cast<const ulonglong2*>(
                            &sX[(rb1 * 16 + r) * 64 + 4 * dc]);
                        acc[r][0] = ffma2(a.x, b00, acc[r][0]);
                        acc[r][0] = ffma2(a.y, b01, acc[r][0]);
                        acc[r][1] = ffma2(a.x, b10, acc[r][1]);
                        acc[r][1] = ffma2(a.y, b11, acc[r][1]);
                    }
                }
                #pragma unroll
                for (int r = 0; r < 16; ++r)
                    #pragma unroll
                    for (int c = 0; c < 2; ++c) {
                        float2 s = unp2(acc[r][c]);
                        float z = s.x + s.y, gp;
                        float hv = gelu_fwd_bwd(z, &gp);
                        int idx = (rb1 * 16 + r) * HI + e0 + 32 * c;
                        sH[idx]  = hv;
                        sGp[idx] = gp;
                    }
            }
            __syncthreads();

            // ---- G2: E = (H @ W2 - Y) * INV_SC. rows mg+i, col o2, K-pairs over e
            {
                U64 eacc[8];
                #pragma unroll
                for (int i = 0; i < 8; ++i) eacc[i] = 0ull;
                #pragma unroll 2
                for (int ep2 = 0; ep2 < 64; ++ep2) {   // 4 e per iter
                    float w0 = sW2[(4 * ep2 + 0) * 66 + o2];
                    float w1 = sW2[(4 * ep2 + 1) * 66 + o2];
                    float w2 = sW2[(4 * ep2 + 2) * 66 + o2];
                    float w3 = sW2[(4 * ep2 + 3) * 66 + o2];
                    U64 b0 = pack2(w0, w1), b1 = pack2(w2, w3);
                    #pragma unroll
                    for (int i = 0; i < 8; ++i) {
                        ulonglong2 a = *reinterpret_cast<const ulonglong2*>(
                            &sH[(mg + i) * HI + 4 * ep2]);
                        eacc[i] = ffma2(a.x, b0, eacc[i]);
                        eacc[i] = ffma2(a.y, b1, eacc[i]);
                    }
                }
                #pragma unroll
                for (int i = 0; i < 8; ++i) {
                    float2 s = unp2(eacc[i]);
                    sE[(mg + i) * DD + o2] = (s.x + s.y - yv[i]) * INV_SC;
                }
            }
            __syncthreads();

            // ---- G3 + G4 merged phase (race-free: G3 reads sH/sE; G4 reads
            //      sE/sW2/sGp and writes only its OWN sGp elements in place)

            // G3: dW2 += H^T @ E  (e-pairs rg*32+2pe, o = lane+32c)
            #pragma unroll 2
            for (int m = 0; m < MT; ++m) {
                float v0 = sE[m * DD + lane];
                float v1 = sE[m * DD + lane + 32];
                U64 b0 = pack2(v0, v0);
                U64 b1 = pack2(v1, v1);
                #pragma unroll
                for (int pe2 = 0; pe2 < 8; ++pe2) {    // 4 e per iter (2 pairs)
                    ulonglong2 a = *reinterpret_cast<const ulonglong2*>(
                        &sH[m * HI + rg * 32 + 4 * pe2]);
                    dW2a[2 * pe2][0]     = ffma2(a.x, b0, dW2a[2 * pe2][0]);
                    dW2a[2 * pe2][1]     = ffma2(a.x, b1, dW2a[2 * pe2][1]);
                    dW2a[2 * pe2 + 1][0] = ffma2(a.y, b0, dW2a[2 * pe2 + 1][0]);
                    dW2a[2 * pe2 + 1][1] = ffma2(a.y, b1, dW2a[2 * pe2 + 1][1]);
                }
            }

            // G4: dH = E @ W2^T ; dZ = dH * gelu'  (written IN PLACE into sGp)
            //     rows hr*16..+16, cols {c0, c0+128}, K-pairs over o
            {
                U64 g4[16][2];
                #pragma unroll
                for (int m = 0; m < 16; ++m) { g4[m][0] = 0ull; g4[m][1] = 0ull; }
                #pragma unroll 2
                for (int op2 = 0; op2 < 16; ++op2) {   // 4 o per iter
                    U64 b0a = ld64s(&sW2[c0 * 66 + 4 * op2]);
                    U64 b0b = ld64s(&sW2[c0 * 66 + 4 * op2 + 2]);
                    U64 b1a = ld64s(&sW2[(c0 + 128) * 66 + 4 * op2]);
                    U64 b1b = ld64s(&sW2[(c0 + 128) * 66 + 4 * op2 + 2]);
                    #pragma unroll
                    for (int m = 0; m < 16; ++m) {
                        ulonglong2 a = *reinterpret_cast<const ulonglong2*>(
                            &sE[(hr * 16 + m) * DD + 4 * op2]);
                        g4[m][0] = ffma2(a.x, b0a, g4[m][0]);
                        g4[m][0] = ffma2(a.y, b0b, g4[m][0]);
                        g4[m][1] = ffma2(a.x, b1a, g4[m][1]);
                        g4[m][1] = ffma2(a.y, b1b, g4[m][1]);
                    }
                }
                #pragma unroll
                for (int m = 0; m < 16; ++m) {
                    float2 s0 = unp2(g4[m][0]);
                    float2 s1 = unp2(g4[m][1]);
                    int idx = (hr * 16 + m) * HI + c0;
                    sGp[idx]       = (s0.x + s0.y) * sGp[idx];
                    sGp[idx + 128] = (s1.x + s1.y) * sGp[idx + 128];
                }
            }
            __syncthreads();

            // ---- G5: dW1 += X^T @ dZ  (dZ now lives in sGp)
            #pragma unroll 2
            for (int m = 0; m < MT; ++m) {
                ulonglong2 x01 = *reinterpret_cast<const ulonglong2*>(&sX[m * 64 + rg * 8]);
                ulonglong2 x23 = *reinterpret_cast<const ulonglong2*>(&sX[m * 64 + rg * 8 + 4]);
                #pragma unroll
                for (int j = 0; j < 8; ++j) {
                    float dz = sGp[m * HI + lane + 32 * j];
                    U64 bz = pack2(dz, dz);
                    dW1a[0][j] = ffma2(x01.x, bz, dW1a[0][j]);
                    dW1a[1][j] = ffma2(x01.y, bz, dW1a[1][j]);
                    dW1a[2][j] = ffma2(x23.x, bz, dW1a[2][j]);
                    dW1a[3][j] = ffma2(x23.y, bz, dW1a[3][j]);
                }
            }
            __syncthreads();   // protect sX/sH/sGp/sE before next tile
        }

        // ---- SGD update (lr = 1.0); W1 pair-major
        #pragma unroll
        for (int pp = 0; pp < 4; ++pp)
            #pragma unroll
            for (int j = 0; j < 8; ++j) {
                int addr = (rg * 4 + pp) * 512 + (lane + 32 * j) * 2;
                float2 w = unp2(ld64s(&sW1p[addr]));
                float2 g = unp2(dW1a[pp][j]);
                st64s(&sW1p[addr], pack2(w.x - g.x, w.y - g.y));
            }
        #pragma unroll
        for (int pe = 0; pe < 16; ++pe) {
            int e = rg * 32 + 2 * pe;
            #pragma unroll
            for (int c = 0; c < 2; ++c) {
                float2 g = unp2(dW2a[pe][c]);
                int o = lane + 32 * c;
                sW2[e * 66 + o]       -= g.x;
                sW2[(e + 1) * 66 + o] -= g.y;
            }
        }
        __syncthreads();
    }

    // Store final adapted weights: W1 pair-major (d), W2 pair-major (e)
    float* gw = g_W + (size_t)bh * (DD * HI + HI * DD);
    for (int i = tid; i < DD * HI; i += 256) gw[i] = sW1p[i];
    for (int i = tid; i < HI * DD; i += 256) {
        int e = i >> 6, o = i & 63;
        gw[DD * HI + (e >> 1) * 128 + o * 2 + (e & 1)] = sW2[e * 66 + o];
    }
}

// ---------------- eval: e-chunked fused MLP (round-6 proven, 460us) ---------
// smem (floats): sQ [64][64] @0 | sW1c [32 d2][64 e][2] @4096 |
//                sW2c [32 e2][64 o][2] @8192 | sHc [64][64] @12288
#define EOFF_Q   0
#define EOFF_W1C 4096
#define EOFF_W2C 8192
#define EOFF_HC  12288
#define EVAL_SMEM_BYTES (16384 * 4)

__global__ __launch_bounds__(256, 2)
void ttt_eval_kernel(const float* __restrict__ qq, float* __restrict__ out) {
    extern __shared__ float sm[];
    float* sQ   = sm + EOFF_Q;
    float* sW1c = sm + EOFF_W1C;
    float* sW2c = sm + EOFF_W2C;
    float* sHc  = sm + EOFF_HC;

    const int tile = blockIdx.x;     // 0..31
    const int bh   = blockIdx.y;     // 0..127
    const int b    = bh >> 4;
    const int h    = bh & 15;
    const int tid  = threadIdx.x;
    const int lane = tid & 31;
    const int rb   = tid >> 5;       // row block (8 rows)

    const float* gw  = g_W + (size_t)bh * (DD * HI + HI * DD);
    const float* gw2 = gw + DD * HI;
    const float* qb  = qq + ((size_t)bh * NS + tile * 64) * DD;

    // load Q tile (plain, float4)
    #pragma unroll
    for (int r = 0; r < 4; ++r) {
        int i4 = tid + 256 * r;
        *reinterpret_cast<float4*>(&sQ[i4 * 4]) =
            *reinterpret_cast<const float4*>(&qb[i4 * 4]);
    }

    U64 oacc[8][2];   // rows rb*8+i, cols {lane, lane+32}; K-pair over e
    #pragma unroll
    for (int i = 0; i < 8; ++i) { oacc[i][0] = 0ull; oacc[i][1] = 0ull; }

    for (int c = 0; c < 4; ++c) {
        __syncthreads();   // previous chunk consumers done (covers sQ fill too)
        // load W1 chunk: rows d2, 128 consecutive floats each
        #pragma unroll
        for (int r = 0; r < 4; ++r) {
            int i4 = tid + 256 * r;
            int d2 = i4 >> 5, off = (i4 & 31) * 4;
            *reinterpret_cast<float4*>(&sW1c[d2 * 128 + off]) =
                *reinterpret_cast<const float4*>(&gw[d2 * 512 + c * 128 + off]);
        }
        // load W2 chunk: contiguous 4096 floats
        #pragma unroll
        for (int r = 0; r < 4; ++r) {
            int i4 = tid + 256 * r;
            *reinterpret_cast<float4*>(&sW2c[i4 * 4]) =
                *reinterpret_cast<const float4*>(&gw2[c * 4096 + i4 * 4]);
        }
        __syncthreads();

        // Z chunk: rows rb*8..+8, e-cols {lane, lane+32}, K-pair over d
        {
            U64 zacc[8][2];
            #pragma unroll
            for (int i = 0; i < 8; ++i) { zacc[i][0] = 0ull; zacc[i][1] = 0ull; }
            #pragma unroll 4
            for (int dc = 0; dc < 16; ++dc) {    // 4 d per iter
                ulonglong2 aa[8];
                #pragma unroll
                for (int r = 0; r < 8; ++r)
                    aa[r] = *reinterpret_cast<const ulonglong2*>(
                        &sQ[(rb * 8 + r) * 64 + 4 * dc]);
                U64 b00 = ld64s(&sW1c[(2 * dc) * 128 + lane * 2]);
                U64 b01 = ld64s(&sW1c[(2 * dc + 1) * 128 + lane * 2]);
                U64 b10 = ld64s(&sW1c[(2 * dc) * 128 + (lane + 32) * 2]);
                U64 b11 = ld64s(&sW1c[(2 * dc + 1) * 128 + (lane + 32) * 2]);
                #pragma unroll
                for (int r = 0; r < 8; ++r) {
                    zacc[r][0] = ffma2(aa[r].x, b00, zacc[r][0]);
                    zacc[r][0] = ffma2(aa[r].y, b01, zacc[r][0]);
                    zacc[r][1] = ffma2(aa[r].x, b10, zacc[r][1]);
                    zacc[r][1] = ffma2(aa[r].y, b11, zacc[r][1]);
                }
            }
            #pragma unroll
            for (int r = 0; r < 8; ++r)
                #pragma unroll
                for (int g = 0; g < 2; ++g) {
                    float2 s = unp2(zacc[r][g]);
                    sHc[(rb * 8 + r) * 64 + lane + 32 * g] = gelu_f(s.x + s.y);
                }
        }
        __syncthreads();

        // O partial: rows rb*8..+8, cols {lane, lane+32}, K-pair over chunk e
        #pragma unroll 2
        for (int ec = 0; ec < 16; ++ec) {       // 4 e per iter (2 e-pairs)
            U64 b00 = ld64s(&sW2c[(2 * ec) * 128 + lane * 2]);
            U64 b01 = ld64s(&sW2c[(2 * ec + 1) * 128 + lane * 2]);
            U64 b10 = ld64s(&sW2c[(2 * ec) * 128 + (lane + 32) * 2]);
            U64 b11 = ld64s(&sW2c[(2 * ec + 1) * 128 + (lane + 32) * 2]);
            #pragma unroll
            for (int i = 0; i < 8; ++i) {
                ulonglong2 a = *reinterpret_cast<const ulonglong2*>(
                    &sHc[(rb * 8 + i) * 64 + 4 * ec]);
                oacc[i][0] = ffma2(a.x, b00, oacc[i][0]);
                oacc[i][0] = ffma2(a.y, b01, oacc[i][0]);
                oacc[i][1] = ffma2(a.x, b10, oacc[i][1]);
                oacc[i][1] = ffma2(a.y, b11, oacc[i][1]);
            }
        }
    }

    // write out[b, n, h*64 + o]
    #pragma unroll
    for (int i = 0; i < 8; ++i) {
        float2 s0 = unp2(oacc[i][0]);
        float2 s1 = unp2(oacc[i][1]);
        int n = tile * 64 + rb * 8 + i;
        size_t base = ((size_t)b * NS + n) * (NH * DD) + h * DD;
        out[base + lane]      = s0.x + s0.y;
        out[base + lane + 32] = s1.x + s1.y;
    }
}

extern "C" void kernel_launch(void* const* d_in, const int* in_sizes, int n_in,
                              void* d_out, int out_size) {
    const float* q  = (const float*)d_in[0];
    const float* k  = (const float*)d_in[1];
    const float* v  = (const float*)d_in[2];
    const float* W1 = (const float*)d_in[3];
    const float* W2 = (const float*)d_in[4];
    float* out = (float*)d_out;

    cudaFuncSetAttribute(ttt_train_kernel,
                         cudaFuncAttributeMaxDynamicSharedMemorySize, TRAIN_SMEM_BYTES);
    cudaFuncSetAttribute(ttt_eval_kernel,
                         cudaFuncAttributeMaxDynamicSharedMemorySize, EVAL_SMEM_BYTES);

    ttt_train_kernel<<<NB * NH, 256, TRAIN_SMEM_BYTES>>>(k, v, W1, W2);
    ttt_eval_kernel<<<dim3(NS / 64, NB * NH), 256, EVAL_SMEM_BYTES>>>(q, out);
}